// round 2
// baseline (speedup 1.0000x reference)
#include <cuda_runtime.h>
#include <cuda_bf16.h>
#include <cstdint>
#include <cstddef>

#define SS 64
#define BB 32
#define HH 1024
#define EE 512
#define VV 32000
#define LL 2
#define SB (SS*BB)                 // 2048
#define BH (BB*HH)                 // 32768
#define LOGITS_N ((size_t)SB*(size_t)VV)

// ---------------- device scratch (no allocations allowed) ----------------
__device__ float g_h0[2][BH];
__device__ float g_h1[2][BH];
__device__ float g_tops[(size_t)SB*HH];                  // [s*B+b][H] fp32
__device__ __nv_bfloat16 g_Ah[(size_t)SB*HH];
__device__ __nv_bfloat16 g_Al[(size_t)SB*HH];
__device__ __nv_bfloat16 g_Bh[(size_t)VV*HH];
__device__ __nv_bfloat16 g_Bl[(size_t)VV*HH];

// ---------------- init hidden ----------------
__global__ void k_init(const float* __restrict__ hidden) {
    int i = blockIdx.x * 256 + threadIdx.x;   // grid 128
    g_h0[0][i] = hidden[i];
    g_h1[0][i] = hidden[BH + i];
}

// ---------------- RNN cell: h_out = tanh(x @ Wx^T + h_prev @ Wh^T + b) ----------------
// grid 128 blocks x 256 threads; block covers 8 h-rows x 32 batches, one output/thread.
template<bool GATHER>
__device__ __forceinline__ void cell(const int* __restrict__ tok,
                                     const float* __restrict__ xsrc, int K1,
                                     const float* __restrict__ hprev,
                                     const float* __restrict__ Wx,
                                     const float* __restrict__ Wh,
                                     const float* __restrict__ bias,
                                     float* __restrict__ hout,
                                     float* __restrict__ tops)
{
    __shared__ float xs[128 * 33];
    __shared__ int   toks[32];
    int tid = threadIdx.x;
    if (GATHER && tid < 32) toks[tid] = tok[tid];
    int bb = tid & 31;
    int hr = tid >> 5;
    int h  = blockIdx.x * 8 + hr;
    float a0 = 0.f, a1 = 0.f, a2 = 0.f, a3 = 0.f;
    const float* wrow0 = Wx + (size_t)h * K1;
    const float* wrow1 = Wh + (size_t)h * HH;

    // segment 0: x part (len K1)
    for (int k0 = 0; k0 < K1; k0 += 128) {
        __syncthreads();
        #pragma unroll
        for (int i = 0; i < 16; i++) {
            int idx = i * 256 + tid;
            int b = idx >> 7, k = idx & 127;
            const float* rb = GATHER ? (xsrc + (size_t)toks[b] * K1)
                                     : (xsrc + (size_t)b * K1);
            xs[k * 33 + b] = rb[k0 + k];
        }
        __syncthreads();
        #pragma unroll
        for (int k = 0; k < 128; k += 4) {
            float4 w = *(const float4*)(wrow0 + k0 + k);
            a0 += w.x * xs[(k + 0) * 33 + bb];
            a1 += w.y * xs[(k + 1) * 33 + bb];
            a2 += w.z * xs[(k + 2) * 33 + bb];
            a3 += w.w * xs[(k + 3) * 33 + bb];
        }
    }
    // segment 1: recurrent part (len HH)
    for (int k0 = 0; k0 < HH; k0 += 128) {
        __syncthreads();
        #pragma unroll
        for (int i = 0; i < 16; i++) {
            int idx = i * 256 + tid;
            int b = idx >> 7, k = idx & 127;
            xs[k * 33 + b] = hprev[(size_t)b * HH + k0 + k];
        }
        __syncthreads();
        #pragma unroll
        for (int k = 0; k < 128; k += 4) {
            float4 w = *(const float4*)(wrow1 + k0 + k);
            a0 += w.x * xs[(k + 0) * 33 + bb];
            a1 += w.y * xs[(k + 1) * 33 + bb];
            a2 += w.z * xs[(k + 2) * 33 + bb];
            a3 += w.w * xs[(k + 3) * 33 + bb];
        }
    }
    float v = tanhf(a0 + a1 + a2 + a3 + bias[h]);
    hout[(size_t)bb * HH + h] = v;
    if (tops) tops[(size_t)bb * HH + h] = v;
}

__global__ void k_l0(int s, const int* __restrict__ tok, const float* __restrict__ emb,
                     const float* __restrict__ Wx0, const float* __restrict__ Wh0,
                     const float* __restrict__ bh0) {
    cell<true>(tok + s * BB, emb, EE, g_h0[s & 1], Wx0, Wh0, bh0,
               g_h0[(s + 1) & 1], nullptr);
}
__global__ void k_l1(int s, const float* __restrict__ Wx1, const float* __restrict__ Wh1,
                     const float* __restrict__ bh1) {
    cell<false>(nullptr, g_h0[(s + 1) & 1], HH, g_h1[s & 1], Wx1, Wh1, bh1,
                g_h1[(s + 1) & 1], g_tops + (size_t)s * BH);
}

// ---------------- hi/lo bf16 split ----------------
__global__ void k_splitA() {
    size_t n = (size_t)SB * HH;
    for (size_t i = blockIdx.x * 256ull + threadIdx.x; i < n; i += gridDim.x * 256ull) {
        float v = g_tops[i];
        __nv_bfloat16 h = __float2bfloat16(v);
        g_Ah[i] = h;
        g_Al[i] = __float2bfloat16(v - __bfloat162float(h));
    }
}
__global__ void k_splitB(const float* __restrict__ W) {
    size_t n = (size_t)VV * HH;
    for (size_t i = blockIdx.x * 256ull + threadIdx.x; i < n; i += gridDim.x * 256ull) {
        float v = W[i];
        __nv_bfloat16 h = __float2bfloat16(v);
        g_Bh[i] = h;
        g_Bl[i] = __float2bfloat16(v - __bfloat162float(h));
    }
}

// ---------------- logits GEMM: C[2048,32000] = A[2048,1024] * B[32000,1024]^T ----------------
#define BM 128
#define BN 64
#define BK 32
#define KW 512   // K/2 u32 words per global row

__device__ __forceinline__ void mma16816(float* c, const unsigned* a, const unsigned* b) {
    asm volatile(
        "mma.sync.aligned.m16n8k16.row.col.f32.bf16.bf16.f32 "
        "{%0,%1,%2,%3},{%4,%5,%6,%7},{%8,%9},{%0,%1,%2,%3};"
        : "+f"(c[0]), "+f"(c[1]), "+f"(c[2]), "+f"(c[3])
        : "r"(a[0]), "r"(a[1]), "r"(a[2]), "r"(a[3]), "r"(b[0]), "r"(b[1]));
}

__global__ void __launch_bounds__(256) k_gemm(const float* __restrict__ bias,
                                              float* __restrict__ C) {
    __shared__ unsigned sAh[BM][17], sAl[BM][17], sBh[BN][17], sBl[BN][17];
    int tid = threadIdx.x;
    int bn = blockIdx.x, bm = blockIdx.y;
    const unsigned* gAh = (const unsigned*)g_Ah + (size_t)(bm * BM) * KW;
    const unsigned* gAl = (const unsigned*)g_Al + (size_t)(bm * BM) * KW;
    const unsigned* gBh = (const unsigned*)g_Bh + (size_t)(bn * BN) * KW;
    const unsigned* gBl = (const unsigned*)g_Bl + (size_t)(bn * BN) * KW;

    int warp = tid >> 5, lane = tid & 31;
    int wm = warp >> 1, wn = warp & 1;        // 4 x 2 warps
    int moff = wm * 32, noff = wn * 32;       // warp tile 32x32
    int g = lane >> 2, t = lane & 3;

    float c[2][4][4];
    #pragma unroll
    for (int i = 0; i < 2; i++)
        #pragma unroll
        for (int j = 0; j < 4; j++)
            #pragma unroll
            for (int r = 0; r < 4; r++) c[i][j][r] = 0.f;

    for (int kt = 0; kt < 32; kt++) {
        #pragma unroll
        for (int i = 0; i < 8; i++) {
            int idx = i * 256 + tid;
            int r = idx >> 4, w = idx & 15;
            sAh[r][w] = gAh[(size_t)r * KW + kt * 16 + w];
            sAl[r][w] = gAl[(size_t)r * KW + kt * 16 + w];
        }
        #pragma unroll
        for (int i = 0; i < 4; i++) {
            int idx = i * 256 + tid;
            int r = idx >> 4, w = idx & 15;
            sBh[r][w] = gBh[(size_t)r * KW + kt * 16 + w];
            sBl[r][w] = gBl[(size_t)r * KW + kt * 16 + w];
        }
        __syncthreads();
        #pragma unroll
        for (int kk = 0; kk < 2; kk++) {
            unsigned ah[2][4], al[2][4], bh[4][2], bl[4][2];
            #pragma unroll
            for (int mt = 0; mt < 2; mt++) {
                int r = moff + mt * 16 + g;
                ah[mt][0] = sAh[r][kk * 8 + t];     ah[mt][1] = sAh[r + 8][kk * 8 + t];
                ah[mt][2] = sAh[r][kk * 8 + t + 4]; ah[mt][3] = sAh[r + 8][kk * 8 + t + 4];
                al[mt][0] = sAl[r][kk * 8 + t];     al[mt][1] = sAl[r + 8][kk * 8 + t];
                al[mt][2] = sAl[r][kk * 8 + t + 4]; al[mt][3] = sAl[r + 8][kk * 8 + t + 4];
            }
            #pragma unroll
            for (int nt = 0; nt < 4; nt++) {
                int r = noff + nt * 8 + g;
                bh[nt][0] = sBh[r][kk * 8 + t]; bh[nt][1] = sBh[r][kk * 8 + t + 4];
                bl[nt][0] = sBl[r][kk * 8 + t]; bl[nt][1] = sBl[r][kk * 8 + t + 4];
            }
            #pragma unroll
            for (int mt = 0; mt < 2; mt++)
                #pragma unroll
                for (int nt = 0; nt < 4; nt++) {
                    mma16816(c[mt][nt], ah[mt], bh[nt]);
                    mma16816(c[mt][nt], al[mt], bh[nt]);
                    mma16816(c[mt][nt], ah[mt], bl[nt]);
                }
        }
        __syncthreads();
    }

    #pragma unroll
    for (int mt = 0; mt < 2; mt++)
        #pragma unroll
        for (int nt = 0; nt < 4; nt++) {
            int m = bm * BM + moff + mt * 16 + g;
            int n = bn * BN + noff + nt * 8 + 2 * t;
            float b0 = bias[n], b1 = bias[n + 1];
            size_t o = (size_t)m * VV + n;
            C[o]     = c[mt][nt][0] + b0;
            C[o + 1] = c[mt][nt][1] + b1;
            size_t o2 = o + (size_t)8 * VV;
            C[o2]     = c[mt][nt][2] + b0;
            C[o2 + 1] = c[mt][nt][3] + b1;
        }
}

// ---------------- hidden_final output ----------------
__global__ void k_hidden(float* __restrict__ out) {
    int i = blockIdx.x * 256 + threadIdx.x;   // grid 128
    out[i]      = g_h0[0][i];   // after 64 steps final buffer index = 64&1 = 0
    out[BH + i] = g_h1[0][i];
}

// ---------------- launch ----------------
extern "C" void kernel_launch(void* const* d_in, const int* in_sizes, int n_in,
                              void* d_out, int out_size) {
    const int*   inputs = (const int*)d_in[0];
    const float* hidden = (const float*)d_in[1];
    const float* emb    = (const float*)d_in[2];
    const float* Wx0    = (const float*)d_in[3];
    const float* Wh0    = (const float*)d_in[4];
    const float* bh0    = (const float*)d_in[5];
    const float* Wx1    = (const float*)d_in[6];
    const float* Wh1    = (const float*)d_in[7];
    const float* bh1    = (const float*)d_in[8];
    const float* Wout   = (const float*)d_in[9];
    const float* bout   = (const float*)d_in[10];
    float* out = (float*)d_out;

    k_init<<<128, 256>>>(hidden);
    k_splitB<<<2048, 256>>>(Wout);          // independent of RNN loop
    for (int s = 0; s < SS; s++) {
        k_l0<<<128, 256>>>(s, inputs, emb, Wx0, Wh0, bh0);
        k_l1<<<128, 256>>>(s, Wx1, Wh1, bh1);
    }
    k_splitA<<<2048, 256>>>();
    dim3 grid(VV / BN, SB / BM);            // 500 x 16
    k_gemm<<<grid, 256>>>(bout, out);
    if ((size_t)out_size >= LOGITS_N + (size_t)LL * BH)
        k_hidden<<<128, 256>>>(out + LOGITS_N);
}

// round 3
// speedup vs baseline: 2.4262x; 2.4262x over previous
#include <cuda_runtime.h>
#include <cuda_bf16.h>
#include <cstdint>
#include <cstddef>

#define SS 64
#define BB 32
#define HH 1024
#define EE 512
#define VV 32000
#define LL 2
#define SB (SS*BB)                 // 2048
#define BH (BB*HH)                 // 32768
#define LOGITS_N ((size_t)SB*(size_t)VV)
#define NB 128
#define TPB 256

// ---------------- device scratch ----------------
__device__ float g_h0[BH];                     // canonical h0 state
__device__ float g_tops[(size_t)SB*HH];        // [s][b][h] layer-1 outputs (also h1 state)
__device__ float g_pA[8][BB][HH];              // layer0 split-K partials
__device__ float g_pB[8][BB][HH];              // layer1 split-K partials
__device__ unsigned g_count = 0;
__device__ unsigned g_flag  = 0;
__device__ __nv_bfloat16 g_Ah[(size_t)SB*HH];
__device__ __nv_bfloat16 g_Al[(size_t)SB*HH];
__device__ __nv_bfloat16 g_Bh[(size_t)VV*HH];
__device__ __nv_bfloat16 g_Bl[(size_t)VV*HH];

// ---------------- grid barrier (all 128 blocks co-resident) ----------------
__device__ __forceinline__ void gbar(unsigned target) {
    __syncthreads();
    if (threadIdx.x == 0) {
        __threadfence();
        unsigned old = atomicAdd(&g_count, 1);
        if (old == NB - 1) {
            g_count = 0;
            __threadfence();
            atomicAdd(&g_flag, 1);
        } else {
            while ((int)(*(volatile unsigned*)&g_flag - target) < 0) { }
        }
    }
    __syncthreads();
}

__device__ __forceinline__ float4 ldcg4(const float* p) {
    return __ldcg((const float4*)p);
}

// smem layout (floats)
#define OFF_WX0 0
#define OFF_WH0 4352            // 64*68
#define OFF_WX1 12800           // +64*132
#define OFF_WH1 21248
#define OFF_BUFA 29696
#define OFF_BUFB 33920
#define SMEM_FLOATS 38144
#define SMEM_BYTES (SMEM_FLOATS*4)

// micro-kernel: a[2][4] += Wrows(2hp,2hp+1) dot x(batches 4bq..4bq+3)
template<int KLEN, int WS>
__device__ __forceinline__ void dotacc(const float* __restrict__ w,
                                       const float* __restrict__ x,
                                       int hp, int bq, float a[2][4]) {
    const float* w0 = w + (2*hp)*WS;
    const float* w1 = w0 + WS;
    const float* xb = x + 4*bq*132;
    #pragma unroll 8
    for (int k = 0; k < KLEN; k += 4) {
        float4 wv0 = *(const float4*)(w0 + k);
        float4 wv1 = *(const float4*)(w1 + k);
        #pragma unroll
        for (int j = 0; j < 4; j++) {
            float4 xv = *(const float4*)(xb + j*132 + k);
            a[0][j] += wv0.x*xv.x + wv0.y*xv.y + wv0.z*xv.z + wv0.w*xv.w;
            a[1][j] += wv1.x*xv.x + wv1.y*xv.y + wv1.z*xv.z + wv1.w*xv.w;
        }
    }
}

// ---------------- persistent RNN kernel ----------------
__global__ void __launch_bounds__(TPB) k_rnn(
    const int* __restrict__ tok, const float* __restrict__ hidden,
    const float* __restrict__ emb,
    const float* __restrict__ Wx0, const float* __restrict__ Wh0, const float* __restrict__ bh0,
    const float* __restrict__ Wx1, const float* __restrict__ Wh1, const float* __restrict__ bh1)
{
    extern __shared__ float sm[];
    float* swx0 = sm + OFF_WX0;
    float* swh0 = sm + OFF_WH0;
    float* swx1 = sm + OFF_WX1;
    float* swh1 = sm + OFF_WH1;
    float* bufA = sm + OFF_BUFA;   // stride 132
    float* bufB = sm + OFF_BUFB;   // stride 132
    __shared__ int toks[32];

    int tid = threadIdx.x;
    int bi  = blockIdx.x;
    int hg  = bi >> 3;     // 0..15 : h rows [hg*64, +64)
    int kc  = bi & 7;      // 0..7  : k-chunk
    unsigned fbase = *(volatile unsigned*)&g_flag;   // stable between launches

    // load weight slices once
    for (int i = tid; i < 64*64; i += TPB) {
        int h = i >> 6, c = i & 63;
        swx0[h*68 + c] = Wx0[(size_t)(hg*64+h)*EE + kc*64 + c];
    }
    for (int i = tid; i < 64*128; i += TPB) {
        int h = i >> 7, c = i & 127;
        size_t gof = (size_t)(hg*64+h)*HH + kc*128 + c;
        swh0[h*132 + c] = Wh0[gof];
        swx1[h*132 + c] = Wx1[gof];
        swh1[h*132 + c] = Wh1[gof];
    }
    // init canonical h0
    {
        int idx = bi*256 + tid;
        g_h0[idx] = hidden[idx];
    }

    int hp = tid >> 3;   // 0..31 -> local h rows 2hp, 2hp+1
    int bq = tid & 7;    // batches 4bq..4bq+3
    unsigned bar = 0;

    gbar(fbase + (++bar));   // h0 init visible to all

    for (int s = 0; s < SS; s++) {
        // ======== phase A ========
        // (a) reduce prev-step layer1 partials -> tops[s-1] (canonical h1)
        if (s > 0) {
            int idx = bi*256 + tid;           // flat [b][h]
            float v = bh1[idx & (HH-1)];
            #pragma unroll
            for (int c = 0; c < 8; c++) v += __ldcg(&g_pB[c][idx>>10][idx & (HH-1)]);
            g_tops[(size_t)(s-1)*BH + idx] = tanhf(v);
        }
        // (b) tiles: emb gather -> bufA[b][0..63], h0 slice -> bufB[b][0..127]
        if (tid < 32) toks[tid] = tok[s*BB + tid];
        __syncthreads();
        for (int i = tid; i < 32*16; i += TPB) {          // emb: 32b x 16 float4
            int b = i >> 4, c4 = i & 15;
            float4 v = *(const float4*)&emb[(size_t)toks[b]*EE + kc*64 + c4*4];
            *(float4*)&bufA[b*132 + c4*4] = v;
        }
        for (int i = tid; i < 32*32; i += TPB) {          // h0: 32b x 32 float4
            int b = i >> 5, c4 = i & 31;
            float4 v = ldcg4(&g_h0[(size_t)b*HH + kc*128 + c4*4]);
            *(float4*)&bufB[b*132 + c4*4] = v;
        }
        __syncthreads();
        // (c) layer0 partials
        {
            float a[2][4] = {{0.f,0.f,0.f,0.f},{0.f,0.f,0.f,0.f}};
            dotacc<64,68>(swx0, bufA, hp, bq, a);
            dotacc<128,132>(swh0, bufB, hp, bq, a);
            int hb = hg*64 + 2*hp;
            #pragma unroll
            for (int j = 0; j < 4; j++)
                *(float2*)&g_pA[kc][4*bq+j][hb] = make_float2(a[0][j], a[1][j]);
        }
        gbar(fbase + (++bar));

        // ======== phase B ========
        // (a) reduce layer0 partials for slice h in [kc*128,+128), tanh -> bufA (+ canonical)
        for (int i = tid; i < 32*32; i += TPB) {
            int b = i >> 5, c4 = i & 31;
            int h = kc*128 + c4*4;
            float4 v = ldcg4(&g_pA[0][b][h]);
            #pragma unroll
            for (int c = 1; c < 8; c++) {
                float4 p = ldcg4(&g_pA[c][b][h]);
                v.x += p.x; v.y += p.y; v.z += p.z; v.w += p.w;
            }
            v.x = tanhf(v.x + bh0[h+0]);
            v.y = tanhf(v.y + bh0[h+1]);
            v.z = tanhf(v.z + bh0[h+2]);
            v.w = tanhf(v.w + bh0[h+3]);
            *(float4*)&bufA[b*132 + c4*4] = v;
            if (hg == 0) *(float4*)&g_h0[(size_t)b*HH + h] = v;   // canonical for next step
        }
        // (b) h1 prev slice -> bufB
        {
            const float* h1src = (s == 0) ? (hidden + BH) : (g_tops + (size_t)(s-1)*BH);
            for (int i = tid; i < 32*32; i += TPB) {
                int b = i >> 5, c4 = i & 31;
                float4 v = ldcg4(&h1src[(size_t)b*HH + kc*128 + c4*4]);
                *(float4*)&bufB[b*132 + c4*4] = v;
            }
        }
        __syncthreads();
        // (c) layer1 partials
        {
            float a[2][4] = {{0.f,0.f,0.f,0.f},{0.f,0.f,0.f,0.f}};
            dotacc<128,132>(swx1, bufA, hp, bq, a);
            dotacc<128,132>(swh1, bufB, hp, bq, a);
            int hb = hg*64 + 2*hp;
            #pragma unroll
            for (int j = 0; j < 4; j++)
                *(float2*)&g_pB[kc][4*bq+j][hb] = make_float2(a[0][j], a[1][j]);
        }
        gbar(fbase + (++bar));
    }

    // final: reduce layer1 partials of step 63 -> tops[63]
    {
        int idx = bi*256 + tid;
        float v = bh1[idx & (HH-1)];
        #pragma unroll
        for (int c = 0; c < 8; c++) v += __ldcg(&g_pB[c][idx>>10][idx & (HH-1)]);
        g_tops[(size_t)63*BH + idx] = tanhf(v);
    }
}

// ---------------- hi/lo bf16 split ----------------
__global__ void k_splitA() {
    size_t n = (size_t)SB * HH;
    for (size_t i = blockIdx.x * 256ull + threadIdx.x; i < n; i += gridDim.x * 256ull) {
        float v = g_tops[i];
        __nv_bfloat16 h = __float2bfloat16(v);
        g_Ah[i] = h;
        g_Al[i] = __float2bfloat16(v - __bfloat162float(h));
    }
}
__global__ void k_splitB(const float* __restrict__ W) {
    size_t n = (size_t)VV * HH;
    for (size_t i = blockIdx.x * 256ull + threadIdx.x; i < n; i += gridDim.x * 256ull) {
        float v = W[i];
        __nv_bfloat16 h = __float2bfloat16(v);
        g_Bh[i] = h;
        g_Bl[i] = __float2bfloat16(v - __bfloat162float(h));
    }
}

// ---------------- logits GEMM ----------------
#define BM 128
#define BN 64
#define KW 512

__device__ __forceinline__ void mma16816(float* c, const unsigned* a, const unsigned* b) {
    asm volatile(
        "mma.sync.aligned.m16n8k16.row.col.f32.bf16.bf16.f32 "
        "{%0,%1,%2,%3},{%4,%5,%6,%7},{%8,%9},{%0,%1,%2,%3};"
        : "+f"(c[0]), "+f"(c[1]), "+f"(c[2]), "+f"(c[3])
        : "r"(a[0]), "r"(a[1]), "r"(a[2]), "r"(a[3]), "r"(b[0]), "r"(b[1]));
}

__global__ void __launch_bounds__(256) k_gemm(const float* __restrict__ bias,
                                              float* __restrict__ C) {
    __shared__ unsigned sAh[BM][17], sAl[BM][17], sBh[BN][17], sBl[BN][17];
    int tid = threadIdx.x;
    int bn = blockIdx.x, bm = blockIdx.y;
    const unsigned* gAh = (const unsigned*)g_Ah + (size_t)(bm * BM) * KW;
    const unsigned* gAl = (const unsigned*)g_Al + (size_t)(bm * BM) * KW;
    const unsigned* gBh = (const unsigned*)g_Bh + (size_t)(bn * BN) * KW;
    const unsigned* gBl = (const unsigned*)g_Bl + (size_t)(bn * BN) * KW;

    int warp = tid >> 5, lane = tid & 31;
    int wm = warp >> 1, wn = warp & 1;
    int moff = wm * 32, noff = wn * 32;
    int g = lane >> 2, t = lane & 3;

    float c[2][4][4];
    #pragma unroll
    for (int i = 0; i < 2; i++)
        #pragma unroll
        for (int j = 0; j < 4; j++)
            #pragma unroll
            for (int r = 0; r < 4; r++) c[i][j][r] = 0.f;

    for (int kt = 0; kt < 32; kt++) {
        #pragma unroll
        for (int i = 0; i < 8; i++) {
            int idx = i * 256 + tid;
            int r = idx >> 4, w = idx & 15;
            sAh[r][w] = gAh[(size_t)r * KW + kt * 16 + w];
            sAl[r][w] = gAl[(size_t)r * KW + kt * 16 + w];
        }
        #pragma unroll
        for (int i = 0; i < 4; i++) {
            int idx = i * 256 + tid;
            int r = idx >> 4, w = idx & 15;
            sBh[r][w] = gBh[(size_t)r * KW + kt * 16 + w];
            sBl[r][w] = gBl[(size_t)r * KW + kt * 16 + w];
        }
        __syncthreads();
        #pragma unroll
        for (int kk = 0; kk < 2; kk++) {
            unsigned ah[2][4], al[2][4], bh[4][2], bl[4][2];
            #pragma unroll
            for (int mt = 0; mt < 2; mt++) {
                int r = moff + mt * 16 + g;
                ah[mt][0] = sAh[r][kk * 8 + t];     ah[mt][1] = sAh[r + 8][kk * 8 + t];
                ah[mt][2] = sAh[r][kk * 8 + t + 4]; ah[mt][3] = sAh[r + 8][kk * 8 + t + 4];
                al[mt][0] = sAl[r][kk * 8 + t];     al[mt][1] = sAl[r + 8][kk * 8 + t];
                al[mt][2] = sAl[r][kk * 8 + t + 4]; al[mt][3] = sAl[r + 8][kk * 8 + t + 4];
            }
            #pragma unroll
            for (int nt = 0; nt < 4; nt++) {
                int r = noff + nt * 8 + g;
                bh[nt][0] = sBh[r][kk * 8 + t]; bh[nt][1] = sBh[r][kk * 8 + t + 4];
                bl[nt][0] = sBl[r][kk * 8 + t]; bl[nt][1] = sBl[r][kk * 8 + t + 4];
            }
            #pragma unroll
            for (int mt = 0; mt < 2; mt++)
                #pragma unroll
                for (int nt = 0; nt < 4; nt++) {
                    mma16816(c[mt][nt], ah[mt], bh[nt]);
                    mma16816(c[mt][nt], al[mt], bh[nt]);
                    mma16816(c[mt][nt], ah[mt], bl[nt]);
                }
        }
        __syncthreads();
    }

    #pragma unroll
    for (int mt = 0; mt < 2; mt++)
        #pragma unroll
        for (int nt = 0; nt < 4; nt++) {
            int m = bm * BM + moff + mt * 16 + g;
            int n = bn * BN + noff + nt * 8 + 2 * t;
            float b0 = bias[n], b1 = bias[n + 1];
            size_t o = (size_t)m * VV + n;
            C[o]     = c[mt][nt][0] + b0;
            C[o + 1] = c[mt][nt][1] + b1;
            size_t o2 = o + (size_t)8 * VV;
            C[o2]     = c[mt][nt][2] + b0;
            C[o2 + 1] = c[mt][nt][3] + b1;
        }
}

// ---------------- hidden_final output ----------------
__global__ void k_hidden(float* __restrict__ out) {
    int i = blockIdx.x * 256 + threadIdx.x;   // grid 128
    out[i]      = g_h0[i];
    out[BH + i] = g_tops[(size_t)63*BH + i];
}

// ---------------- launch ----------------
extern "C" void kernel_launch(void* const* d_in, const int* in_sizes, int n_in,
                              void* d_out, int out_size) {
    const int*   inputs = (const int*)d_in[0];
    const float* hidden = (const float*)d_in[1];
    const float* emb    = (const float*)d_in[2];
    const float* Wx0    = (const float*)d_in[3];
    const float* Wh0    = (const float*)d_in[4];
    const float* bh0    = (const float*)d_in[5];
    const float* Wx1    = (const float*)d_in[6];
    const float* Wh1    = (const float*)d_in[7];
    const float* bh1    = (const float*)d_in[8];
    const float* Wout   = (const float*)d_in[9];
    const float* bout   = (const float*)d_in[10];
    float* out = (float*)d_out;

    static bool attr_set = false;
    if (!attr_set) {
        cudaFuncSetAttribute(k_rnn, cudaFuncAttributeMaxDynamicSharedMemorySize, SMEM_BYTES);
        attr_set = true;
    }

    k_splitB<<<2048, 256>>>(Wout);
    k_rnn<<<NB, TPB, SMEM_BYTES>>>(inputs, hidden, emb, Wx0, Wh0, bh0, Wx1, Wh1, bh1);
    k_splitA<<<2048, 256>>>();
    dim3 grid(VV / BN, SB / BM);
    k_gemm<<<grid, 256>>>(bout, out);
    if ((size_t)out_size >= LOGITS_N + (size_t)LL * BH)
        k_hidden<<<128, 256>>>(out + LOGITS_N);
}

// round 4
// speedup vs baseline: 2.9657x; 1.2224x over previous
#include <cuda_runtime.h>
#include <cuda_bf16.h>
#include <cstdint>
#include <cstddef>

#define SS 64
#define BB 32
#define HH 1024
#define EE 512
#define VV 32000
#define LL 2
#define SB (SS*BB)                 // 2048
#define BH (BB*HH)                 // 32768
#define LOGITS_N ((size_t)SB*(size_t)VV)
#define NB 128
#define TPB 256

// ---------------- device scratch ----------------
__device__ float g_h0[BH];
__device__ float g_tops[(size_t)SB*HH];
__device__ float g_pA[8][BB][HH];
__device__ float g_pB[8][BB][HH];
__device__ unsigned g_count = 0;
__device__ unsigned g_flag  = 0;
__device__ __nv_bfloat16 g_Ah[(size_t)SB*HH];
__device__ __nv_bfloat16 g_Al[(size_t)SB*HH];
__device__ __nv_bfloat16 g_Bh[(size_t)VV*HH];
__device__ __nv_bfloat16 g_Bl[(size_t)VV*HH];

// ---------------- grid barrier ----------------
__device__ __forceinline__ void gbar(unsigned target) {
    __syncthreads();
    if (threadIdx.x == 0) {
        __threadfence();
        unsigned old = atomicAdd(&g_count, 1);
        if (old == NB - 1) {
            g_count = 0;
            __threadfence();
            atomicAdd(&g_flag, 1);
        } else {
            while ((int)(*(volatile unsigned*)&g_flag - target) < 0) { }
        }
    }
    __syncthreads();
}

__device__ __forceinline__ float4 ldcg4(const float* p) {
    return __ldcg((const float4*)p);
}

// ---------------- persistent RNN (unchanged from round 3) ----------------
#define OFF_WX0 0
#define OFF_WH0 4352
#define OFF_WX1 12800
#define OFF_WH1 21248
#define OFF_BUFA 29696
#define OFF_BUFB 33920
#define SMEM_FLOATS 38144
#define SMEM_BYTES (SMEM_FLOATS*4)

template<int KLEN, int WS>
__device__ __forceinline__ void dotacc(const float* __restrict__ w,
                                       const float* __restrict__ x,
                                       int hp, int bq, float a[2][4]) {
    const float* w0 = w + (2*hp)*WS;
    const float* w1 = w0 + WS;
    const float* xb = x + 4*bq*132;
    #pragma unroll 8
    for (int k = 0; k < KLEN; k += 4) {
        float4 wv0 = *(const float4*)(w0 + k);
        float4 wv1 = *(const float4*)(w1 + k);
        #pragma unroll
        for (int j = 0; j < 4; j++) {
            float4 xv = *(const float4*)(xb + j*132 + k);
            a[0][j] += wv0.x*xv.x + wv0.y*xv.y + wv0.z*xv.z + wv0.w*xv.w;
            a[1][j] += wv1.x*xv.x + wv1.y*xv.y + wv1.z*xv.z + wv1.w*xv.w;
        }
    }
}

__global__ void __launch_bounds__(TPB) k_rnn(
    const int* __restrict__ tok, const float* __restrict__ hidden,
    const float* __restrict__ emb,
    const float* __restrict__ Wx0, const float* __restrict__ Wh0, const float* __restrict__ bh0,
    const float* __restrict__ Wx1, const float* __restrict__ Wh1, const float* __restrict__ bh1)
{
    extern __shared__ float sm[];
    float* swx0 = sm + OFF_WX0;
    float* swh0 = sm + OFF_WH0;
    float* swx1 = sm + OFF_WX1;
    float* swh1 = sm + OFF_WH1;
    float* bufA = sm + OFF_BUFA;
    float* bufB = sm + OFF_BUFB;
    __shared__ int toks[32];

    int tid = threadIdx.x;
    int bi  = blockIdx.x;
    int hg  = bi >> 3;
    int kc  = bi & 7;
    unsigned fbase = *(volatile unsigned*)&g_flag;

    for (int i = tid; i < 64*64; i += TPB) {
        int h = i >> 6, c = i & 63;
        swx0[h*68 + c] = Wx0[(size_t)(hg*64+h)*EE + kc*64 + c];
    }
    for (int i = tid; i < 64*128; i += TPB) {
        int h = i >> 7, c = i & 127;
        size_t gof = (size_t)(hg*64+h)*HH + kc*128 + c;
        swh0[h*132 + c] = Wh0[gof];
        swx1[h*132 + c] = Wx1[gof];
        swh1[h*132 + c] = Wh1[gof];
    }
    {
        int idx = bi*256 + tid;
        g_h0[idx] = hidden[idx];
    }

    int hp = tid >> 3;
    int bq = tid & 7;
    unsigned bar = 0;

    gbar(fbase + (++bar));

    for (int s = 0; s < SS; s++) {
        if (s > 0) {
            int idx = bi*256 + tid;
            float v = bh1[idx & (HH-1)];
            #pragma unroll
            for (int c = 0; c < 8; c++) v += __ldcg(&g_pB[c][idx>>10][idx & (HH-1)]);
            g_tops[(size_t)(s-1)*BH + idx] = tanhf(v);
        }
        if (tid < 32) toks[tid] = tok[s*BB + tid];
        __syncthreads();
        for (int i = tid; i < 32*16; i += TPB) {
            int b = i >> 4, c4 = i & 15;
            float4 v = *(const float4*)&emb[(size_t)toks[b]*EE + kc*64 + c4*4];
            *(float4*)&bufA[b*132 + c4*4] = v;
        }
        for (int i = tid; i < 32*32; i += TPB) {
            int b = i >> 5, c4 = i & 31;
            float4 v = ldcg4(&g_h0[(size_t)b*HH + kc*128 + c4*4]);
            *(float4*)&bufB[b*132 + c4*4] = v;
        }
        __syncthreads();
        {
            float a[2][4] = {{0.f,0.f,0.f,0.f},{0.f,0.f,0.f,0.f}};
            dotacc<64,68>(swx0, bufA, hp, bq, a);
            dotacc<128,132>(swh0, bufB, hp, bq, a);
            int hb = hg*64 + 2*hp;
            #pragma unroll
            for (int j = 0; j < 4; j++)
                *(float2*)&g_pA[kc][4*bq+j][hb] = make_float2(a[0][j], a[1][j]);
        }
        gbar(fbase + (++bar));

        for (int i = tid; i < 32*32; i += TPB) {
            int b = i >> 5, c4 = i & 31;
            int h = kc*128 + c4*4;
            float4 v = ldcg4(&g_pA[0][b][h]);
            #pragma unroll
            for (int c = 1; c < 8; c++) {
                float4 p = ldcg4(&g_pA[c][b][h]);
                v.x += p.x; v.y += p.y; v.z += p.z; v.w += p.w;
            }
            v.x = tanhf(v.x + bh0[h+0]);
            v.y = tanhf(v.y + bh0[h+1]);
            v.z = tanhf(v.z + bh0[h+2]);
            v.w = tanhf(v.w + bh0[h+3]);
            *(float4*)&bufA[b*132 + c4*4] = v;
            if (hg == 0) *(float4*)&g_h0[(size_t)b*HH + h] = v;
        }
        {
            const float* h1src = (s == 0) ? (hidden + BH) : (g_tops + (size_t)(s-1)*BH);
            for (int i = tid; i < 32*32; i += TPB) {
                int b = i >> 5, c4 = i & 31;
                float4 v = ldcg4(&h1src[(size_t)b*HH + kc*128 + c4*4]);
                *(float4*)&bufB[b*132 + c4*4] = v;
            }
        }
        __syncthreads();
        {
            float a[2][4] = {{0.f,0.f,0.f,0.f},{0.f,0.f,0.f,0.f}};
            dotacc<128,132>(swx1, bufA, hp, bq, a);
            dotacc<128,132>(swh1, bufB, hp, bq, a);
            int hb = hg*64 + 2*hp;
            #pragma unroll
            for (int j = 0; j < 4; j++)
                *(float2*)&g_pB[kc][4*bq+j][hb] = make_float2(a[0][j], a[1][j]);
        }
        gbar(fbase + (++bar));
    }

    {
        int idx = bi*256 + tid;
        float v = bh1[idx & (HH-1)];
        #pragma unroll
        for (int c = 0; c < 8; c++) v += __ldcg(&g_pB[c][idx>>10][idx & (HH-1)]);
        g_tops[(size_t)63*BH + idx] = tanhf(v);
    }
}

// ---------------- hi/lo bf16 split ----------------
__global__ void k_splitA() {
    size_t n = (size_t)SB * HH;
    for (size_t i = blockIdx.x * 256ull + threadIdx.x; i < n; i += gridDim.x * 256ull) {
        float v = g_tops[i];
        __nv_bfloat16 h = __float2bfloat16(v);
        g_Ah[i] = h;
        g_Al[i] = __float2bfloat16(v - __bfloat162float(h));
    }
}
__global__ void k_splitB(const float* __restrict__ W) {
    size_t n = (size_t)VV * HH;
    for (size_t i = blockIdx.x * 256ull + threadIdx.x; i < n; i += gridDim.x * 256ull) {
        float v = W[i];
        __nv_bfloat16 h = __float2bfloat16(v);
        g_Bh[i] = h;
        g_Bl[i] = __float2bfloat16(v - __bfloat162float(h));
    }
}

// ---------------- logits GEMM: ldmatrix + cp.async double-buffer ----------------
// C[2048,32000] = A[2048,1024] * B[32000,1024]^T, 3-term bf16 split.
// Block tile 128x128x32, 8 warps (2m x 4n), warp tile 64x32.
#define GROW 40                       // smem row stride in bf16 (80B, LDSM conflict-free)
#define STAGE_U (512*GROW)            // 256 A rows + 256 B rows per stage (bf16 units)
#define GSMEM_BYTES (2*STAGE_U*2)     // 81920

__device__ __forceinline__ void cpa16(unsigned saddr, const void* g) {
    asm volatile("cp.async.cg.shared.global [%0], [%1], 16;" :: "r"(saddr), "l"(g));
}
__device__ __forceinline__ void cp_commit() { asm volatile("cp.async.commit_group;"); }
__device__ __forceinline__ void cp_wait0()  { asm volatile("cp.async.wait_group 0;"); }

__device__ __forceinline__ void ldsm4(unsigned addr, unsigned* r) {
    asm volatile("ldmatrix.sync.aligned.m8n8.x4.shared.b16 {%0,%1,%2,%3}, [%4];"
        : "=r"(r[0]), "=r"(r[1]), "=r"(r[2]), "=r"(r[3]) : "r"(addr));
}
__device__ __forceinline__ void mma16816(float* c, const unsigned* a, const unsigned* b) {
    asm volatile(
        "mma.sync.aligned.m16n8k16.row.col.f32.bf16.bf16.f32 "
        "{%0,%1,%2,%3},{%4,%5,%6,%7},{%8,%9},{%0,%1,%2,%3};"
        : "+f"(c[0]), "+f"(c[1]), "+f"(c[2]), "+f"(c[3])
        : "r"(a[0]), "r"(a[1]), "r"(a[2]), "r"(a[3]), "r"(b[0]), "r"(b[1]));
}

__global__ void __launch_bounds__(256) k_gemm(const float* __restrict__ bias,
                                              float* __restrict__ C) {
    extern __shared__ __nv_bfloat16 gsm[];
    unsigned smem_base = (unsigned)__cvta_generic_to_shared(gsm);

    int tid = threadIdx.x;
    int bm = blockIdx.x;       // fast dim: wave shares B via L2
    int bn = blockIdx.y;

    const __nv_bfloat16* pAh = g_Ah + (size_t)(bm*128)*HH;
    const __nv_bfloat16* pAl = g_Al + (size_t)(bm*128)*HH;
    const __nv_bfloat16* pBh = g_Bh + (size_t)(bn*128)*HH;
    const __nv_bfloat16* pBl = g_Bl + (size_t)(bn*128)*HH;

    auto load_stage = [&](int st, int kt) {
        unsigned base = smem_base + (unsigned)(st*STAGE_U)*2;
        #pragma unroll
        for (int i = 0; i < 4; i++) {
            int id = tid + i*256;
            int row = id >> 2, c = id & 3;
            const __nv_bfloat16* src = ((row < 128) ? pAh + (size_t)row*HH
                                                    : pAl + (size_t)(row-128)*HH)
                                       + kt*32 + c*8;
            cpa16(base + (unsigned)(row*GROW + c*8)*2, src);
        }
        #pragma unroll
        for (int i = 0; i < 4; i++) {
            int id = tid + i*256;
            int row = id >> 2, c = id & 3;
            const __nv_bfloat16* src = ((row < 128) ? pBh + (size_t)row*HH
                                                    : pBl + (size_t)(row-128)*HH)
                                       + kt*32 + c*8;
            cpa16(base + (unsigned)(256*GROW + row*GROW + c*8)*2, src);
        }
        cp_commit();
    };

    int lane = tid & 31, warp = tid >> 5;
    int wm = warp >> 2;            // 0..1
    int wn = warp & 3;             // 0..3
    int moff = wm * 64, noff = wn * 32;

    int arow = lane & 15;
    int akh  = (lane >= 16) ? 8 : 0;
    int brow = (lane & 7) + ((lane >= 16) ? 8 : 0);
    int bkh  = (lane & 8) ? 8 : 0;

    float acc[4][4][4];
    #pragma unroll
    for (int mt = 0; mt < 4; mt++)
        #pragma unroll
        for (int nt = 0; nt < 4; nt++)
            #pragma unroll
            for (int r = 0; r < 4; r++) acc[mt][nt][r] = 0.f;

    load_stage(0, 0);

    #pragma unroll 1
    for (int kt = 0; kt < 32; kt++) {
        cp_wait0();
        __syncthreads();
        if (kt + 1 < 32) load_stage((kt + 1) & 1, kt + 1);

        unsigned aB = smem_base + (unsigned)((kt & 1)*STAGE_U)*2;
        unsigned bB = aB + (unsigned)(256*GROW)*2;

        #pragma unroll
        for (int kk = 0; kk < 2; kk++) {
            unsigned ah[4][4], al[4][4], bh[2][4], bl[2][4];
            #pragma unroll
            for (int mt = 0; mt < 4; mt++) {
                unsigned ra = aB + (unsigned)((moff + mt*16 + arow)*GROW + kk*16 + akh)*2;
                ldsm4(ra, ah[mt]);
                ldsm4(ra + (unsigned)(128*GROW)*2, al[mt]);
            }
            #pragma unroll
            for (int q = 0; q < 2; q++) {
                unsigned rb = bB + (unsigned)((noff + q*16 + brow)*GROW + kk*16 + bkh)*2;
                ldsm4(rb, bh[q]);
                ldsm4(rb + (unsigned)(128*GROW)*2, bl[q]);
            }
            #pragma unroll
            for (int mt = 0; mt < 4; mt++)
                #pragma unroll
                for (int nt = 0; nt < 4; nt++) {
                    const unsigned* vh = &bh[nt >> 1][(nt & 1)*2];
                    const unsigned* vl = &bl[nt >> 1][(nt & 1)*2];
                    mma16816(acc[mt][nt], ah[mt], vh);
                    mma16816(acc[mt][nt], al[mt], vh);
                    mma16816(acc[mt][nt], ah[mt], vl);
                }
        }
        __syncthreads();
    }

    int g = lane >> 2, t2 = lane & 3;
    #pragma unroll
    for (int mt = 0; mt < 4; mt++)
        #pragma unroll
        for (int nt = 0; nt < 4; nt++) {
            int m = bm*128 + moff + mt*16 + g;
            int n = bn*128 + noff + nt*8 + t2*2;
            float b0 = __ldg(&bias[n]), b1 = __ldg(&bias[n+1]);
            size_t o = (size_t)m * VV + n;
            C[o]     = acc[mt][nt][0] + b0;
            C[o + 1] = acc[mt][nt][1] + b1;
            size_t o2 = o + (size_t)8 * VV;
            C[o2]     = acc[mt][nt][2] + b0;
            C[o2 + 1] = acc[mt][nt][3] + b1;
        }
}

// ---------------- hidden_final output ----------------
__global__ void k_hidden(float* __restrict__ out) {
    int i = blockIdx.x * 256 + threadIdx.x;
    out[i]      = g_h0[i];
    out[BH + i] = g_tops[(size_t)63*BH + i];
}

// ---------------- launch ----------------
extern "C" void kernel_launch(void* const* d_in, const int* in_sizes, int n_in,
                              void* d_out, int out_size) {
    const int*   inputs = (const int*)d_in[0];
    const float* hidden = (const float*)d_in[1];
    const float* emb    = (const float*)d_in[2];
    const float* Wx0    = (const float*)d_in[3];
    const float* Wh0    = (const float*)d_in[4];
    const float* bh0    = (const float*)d_in[5];
    const float* Wx1    = (const float*)d_in[6];
    const float* Wh1    = (const float*)d_in[7];
    const float* bh1    = (const float*)d_in[8];
    const float* Wout   = (const float*)d_in[9];
    const float* bout   = (const float*)d_in[10];
    float* out = (float*)d_out;

    static bool attr_set = false;
    if (!attr_set) {
        cudaFuncSetAttribute(k_rnn,  cudaFuncAttributeMaxDynamicSharedMemorySize, SMEM_BYTES);
        cudaFuncSetAttribute(k_gemm, cudaFuncAttributeMaxDynamicSharedMemorySize, GSMEM_BYTES);
        attr_set = true;
    }

    k_splitB<<<2048, 256>>>(Wout);
    k_rnn<<<NB, TPB, SMEM_BYTES>>>(inputs, hidden, emb, Wx0, Wh0, bh0, Wx1, Wh1, bh1);
    k_splitA<<<2048, 256>>>();
    dim3 grid(SB / 128, VV / 128);   // (16, 250): bm fast -> wave shares B tiles
    k_gemm<<<grid, 256, GSMEM_BYTES>>>(bout, out);
    if ((size_t)out_size >= LOGITS_N + (size_t)LL * BH)
        k_hidden<<<128, 256>>>(out + LOGITS_N);
}